// round 13
// baseline (speedup 1.0000x reference)
#include <cuda_runtime.h>
#include <cstdint>
#include <math.h>

#define BATCH 2
#define SEQ   2048
#define DM    768
#define NS    64
#define MROWS (BATCH*SEQ)   // 4096

// Scratch (device globals)
__device__ float g_xn [MROWS*DM];   // layernorm output  [m][d]
__device__ float g_u  [MROWS*DM];   // in_proj output    [m][d]
__device__ float g_ysT[DM*MROWS];   // scan output, transposed [d][m]

__device__ __forceinline__ uint32_t smem_u32(const void* p) {
    uint32_t a;
    asm("{ .reg .u64 t; cvta.to.shared.u64 t, %1; cvt.u32.u64 %0, t; }"
        : "=r"(a) : "l"(p));
    return a;
}
__device__ __forceinline__ void cp16(uint32_t dst, const void* src) {
    asm volatile("cp.async.cg.shared.global [%0], [%1], 16;"
                 :: "r"(dst), "l"(src) : "memory");
}
#define CP_COMMIT() asm volatile("cp.async.commit_group;" ::: "memory")
#define CP_WAIT1()  asm volatile("cp.async.wait_group 1;" ::: "memory")

// ---------------------------------------------------------------------------
// LayerNorm: one warp per row
// ---------------------------------------------------------------------------
__global__ void ln_kernel(const float* __restrict__ x,
                          const float* __restrict__ gamma,
                          const float* __restrict__ beta,
                          float* __restrict__ out) {
    int w = threadIdx.x >> 5, lane = threadIdx.x & 31;
    int row = blockIdx.x * 8 + w;
    const float4* xr = (const float4*)(x + (size_t)row * DM);
    float4 v[6];
    float s = 0.f, s2 = 0.f;
    #pragma unroll
    for (int i = 0; i < 6; i++) {
        v[i] = xr[lane + 32 * i];
        s  += v[i].x + v[i].y + v[i].z + v[i].w;
        s2 += v[i].x*v[i].x + v[i].y*v[i].y + v[i].z*v[i].z + v[i].w*v[i].w;
    }
    #pragma unroll
    for (int o = 16; o; o >>= 1) {
        s  += __shfl_xor_sync(0xffffffffu, s,  o);
        s2 += __shfl_xor_sync(0xffffffffu, s2, o);
    }
    float mu  = s * (1.0f / DM);
    float var = s2 * (1.0f / DM) - mu * mu;
    float inv = rsqrtf(var + 1e-5f);
    const float4* g4 = (const float4*)gamma;
    const float4* b4 = (const float4*)beta;
    float4* orow = (float4*)(out + (size_t)row * DM);
    #pragma unroll
    for (int i = 0; i < 6; i++) {
        float4 g = g4[lane + 32 * i], b = b4[lane + 32 * i], o;
        o.x = (v[i].x - mu) * inv * g.x + b.x;
        o.y = (v[i].y - mu) * inv * g.y + b.y;
        o.z = (v[i].z - mu) * inv * g.z + b.z;
        o.w = (v[i].w - mu) * inv * g.w + b.w;
        orow[lane + 32 * i] = o;
    }
}

// ---------------------------------------------------------------------------
// tf32 mma.sync GEMM, cp.async 3-stage pipeline.
// Block 64x64, 128 threads (4 warps, 2m x 2n), warp tile 32x32.
// Grid 768 -> ~5.2 CTAs/SM resident (single wave), 2x latency hiding vs 128x64.
// ---------------------------------------------------------------------------
#define STAGES 3

template<bool A_TRANS, bool ADD_RES>
__global__ __launch_bounds__(128, 6)
void gemm_mma(const float* __restrict__ A, const float* __restrict__ W,
              const float* __restrict__ bias, const float* __restrict__ res,
              float* __restrict__ C) {
    constexpr int AS_FLOATS = A_TRANS ? (16 * 72) : (64 * 20);
    constexpr int BS_FLOATS = 64 * 20;
    __shared__ float As[STAGES][AS_FLOATS];
    __shared__ float Bs[STAGES][BS_FLOATS];

    const int tid = threadIdx.x;
    const int w = tid >> 5, lane = tid & 31;
    const int wm = (w & 1) * 32, wn = (w >> 1) * 32;
    const int g = lane >> 2, t = lane & 3;
    const int m0 = blockIdx.y * 64, n0 = blockIdx.x * 64;

    const uint32_t sA = smem_u32(&As[0][0]);
    const uint32_t sB = smem_u32(&Bs[0][0]);

    // per-thread cp.async mappings (fixed across kt): 2 float4 for A, 2 for B
    int aoff[2];
    const float* asrc[2];
    #pragma unroll
    for (int j = 0; j < 2; j++) {
        int f4 = tid + j * 128;  // 0..255
        if (A_TRANS) {
            int r = f4 >> 4, c = (f4 & 15) * 4;   // r:0..15, c:0..60
            aoff[j] = r * 72 + c;
            asrc[j] = A + (size_t)r * MROWS + m0 + c;
        } else {
            int r = f4 >> 2, c4 = f4 & 3;          // r:0..63
            aoff[j] = r * 20 + c4 * 4;
            asrc[j] = A + (size_t)(m0 + r) * DM + c4 * 4;
        }
    }
    int boff[2];
    const float* bsrc[2];
    #pragma unroll
    for (int j = 0; j < 2; j++) {
        int f4 = tid + j * 128;  // 0..255
        int r = f4 >> 2, c4 = f4 & 3;
        boff[j] = r * 20 + c4 * 4;
        bsrc[j] = W + (size_t)(n0 + r) * DM + c4 * 4;
    }

    auto issue = [&](int kt) {
        int s = kt % STAGES;
        #pragma unroll
        for (int j = 0; j < 2; j++) {
            uint32_t dst = sA + (uint32_t)(s * AS_FLOATS + aoff[j]) * 4u;
            const float* src = asrc[j] + (A_TRANS ? (size_t)kt * 16 * MROWS
                                                  : (size_t)kt * 16);
            cp16(dst, src);
        }
        #pragma unroll
        for (int j = 0; j < 2; j++) {
            uint32_t dst = sB + (uint32_t)(s * BS_FLOATS + boff[j]) * 4u;
            cp16(dst, bsrc[j] + (size_t)kt * 16);
        }
    };

    issue(0); CP_COMMIT();
    issue(1); CP_COMMIT();

    float acc[2][4][4] = {};

    const int NKT = DM / 16;   // 48
    for (int kt = 0; kt < NKT; kt++) {
        CP_WAIT1();
        __syncthreads();
        int s = kt % STAGES;
        #pragma unroll
        for (int ks = 0; ks < 2; ks++) {
            uint32_t af[2][4], bf[4][2];
            #pragma unroll
            for (int mt = 0; mt < 2; mt++) {
                int m = wm + mt * 16;
                if (A_TRANS) {
                    af[mt][0] = __float_as_uint(As[s][(ks*8 + t)     * 72 + m + g]);
                    af[mt][1] = __float_as_uint(As[s][(ks*8 + t)     * 72 + m + g + 8]);
                    af[mt][2] = __float_as_uint(As[s][(ks*8 + t + 4) * 72 + m + g]);
                    af[mt][3] = __float_as_uint(As[s][(ks*8 + t + 4) * 72 + m + g + 8]);
                } else {
                    af[mt][0] = __float_as_uint(As[s][(m + g)     * 20 + ks*8 + t]);
                    af[mt][1] = __float_as_uint(As[s][(m + g + 8) * 20 + ks*8 + t]);
                    af[mt][2] = __float_as_uint(As[s][(m + g)     * 20 + ks*8 + t + 4]);
                    af[mt][3] = __float_as_uint(As[s][(m + g + 8) * 20 + ks*8 + t + 4]);
                }
            }
            #pragma unroll
            for (int nt = 0; nt < 4; nt++) {
                int n = wn + nt * 8;
                bf[nt][0] = __float_as_uint(Bs[s][(n + g) * 20 + ks*8 + t]);
                bf[nt][1] = __float_as_uint(Bs[s][(n + g) * 20 + ks*8 + t + 4]);
            }
            #pragma unroll
            for (int mt = 0; mt < 2; mt++)
                #pragma unroll
                for (int nt = 0; nt < 4; nt++)
                    asm volatile(
                        "mma.sync.aligned.m16n8k8.row.col.f32.tf32.tf32.f32 "
                        "{%0,%1,%2,%3}, {%4,%5,%6,%7}, {%8,%9}, {%0,%1,%2,%3};"
                        : "+f"(acc[mt][nt][0]), "+f"(acc[mt][nt][1]),
                          "+f"(acc[mt][nt][2]), "+f"(acc[mt][nt][3])
                        : "r"(af[mt][0]), "r"(af[mt][1]), "r"(af[mt][2]), "r"(af[mt][3]),
                          "r"(bf[nt][0]), "r"(bf[nt][1]));
        }
        if (kt + 2 < NKT) issue(kt + 2);
        CP_COMMIT();
    }

    // Epilogue
    #pragma unroll
    for (int mt = 0; mt < 2; mt++) {
        int r0 = m0 + wm + mt * 16 + g;
        #pragma unroll
        for (int nt = 0; nt < 4; nt++) {
            int cn = n0 + wn + nt * 8 + t * 2;
            float2 bb = *(const float2*)(bias + cn);
            float2 o0 = { acc[mt][nt][0] + bb.x, acc[mt][nt][1] + bb.y };
            float2 o1 = { acc[mt][nt][2] + bb.x, acc[mt][nt][3] + bb.y };
            if (ADD_RES) {
                float2 ra = *(const float2*)(res + (size_t)r0 * DM + cn);
                float2 rb = *(const float2*)(res + (size_t)(r0 + 8) * DM + cn);
                o0.x += ra.x; o0.y += ra.y; o1.x += rb.x; o1.y += rb.y;
            }
            *(float2*)(C + (size_t)r0 * DM + cn) = o0;
            *(float2*)(C + (size_t)(r0 + 8) * DM + cn) = o1;
        }
    }
}

// ---------------------------------------------------------------------------
// SSM scan, instruction-minimized, distribution-balanced (R12).
// Block = 128 threads = 4 warps = 4 channels, grid 384.
// One warp per (b,d): scaled recurrence e = Ab*e + u (2 states/lane),
// partial p = Cb0*e0 + Cb1*e1 into smem transpose (pad 33); lane L sums
// row L -> y[t0+L], D-term via lane-local u register.
// ---------------------------------------------------------------------------
__global__ __launch_bounds__(128)
void scan_kernel(const float* __restrict__ u,
                 const float* __restrict__ log_A,
                 const float* __restrict__ B_p,
                 const float* __restrict__ C_p,
                 const float* __restrict__ D_p,
                 const float* __restrict__ log_dt,
                 float* __restrict__ ysT) {
    __shared__ float red[4][32 * 33];

    int tid = threadIdx.x, w = tid >> 5, lane = tid & 31;
    int blk = blockIdx.x;
    int b  = blk / (DM / 4);
    int d  = (blk % (DM / 4)) * 4 + w;
    int n0 = lane * 2;

    float dt  = expf(log_dt[d]);
    float Ab0 = expf(dt * (-expf(log_A[d * NS + n0])));
    float Ab1 = expf(dt * (-expf(log_A[d * NS + n0 + 1])));
    float Cb0 = C_p[d * NS + n0]     * B_p[d * NS + n0]     * dt;
    float Cb1 = C_p[d * NS + n0 + 1] * B_p[d * NS + n0 + 1] * dt;
    float Dd  = D_p[d];

    const float* up = u + (size_t)b * SEQ * DM + d;
    float* yT = ysT + (size_t)d * MROWS + (size_t)b * SEQ;
    float* sm = &red[w][0];

    float e0 = 0.f, e1 = 0.f;
    float ul = __ldg(up + (size_t)lane * DM);

    for (int t0 = 0; t0 < SEQ; t0 += 32) {
        float uln = 0.f;
        if (t0 + 32 < SEQ)
            uln = __ldg(up + (size_t)(t0 + 32 + lane) * DM);

        #pragma unroll
        for (int i = 0; i < 32; i++) {
            float ut = __shfl_sync(0xffffffffu, ul, i);
            e0 = fmaf(Ab0, e0, ut);
            e1 = fmaf(Ab1, e1, ut);
            sm[i * 33 + lane] = fmaf(Cb0, e0, Cb1 * e1);
        }
        __syncwarp();

        float a0 = 0.f, a1 = 0.f, a2 = 0.f, a3 = 0.f;
        const float* row = sm + lane * 33;
        #pragma unroll
        for (int j = 0; j < 32; j += 4) {
            a0 += row[j]; a1 += row[j + 1]; a2 += row[j + 2]; a3 += row[j + 3];
        }
        yT[t0 + lane] = fmaf(Dd, ul, (a0 + a1) + (a2 + a3));
        __syncwarp();

        ul = uln;
    }
}

// ---------------------------------------------------------------------------
extern "C" void kernel_launch(void* const* d_in, const int* in_sizes, int n_in,
                              void* d_out, int out_size) {
    const float* x        = (const float*)d_in[0];
    const float* ln_gamma = (const float*)d_in[1];
    const float* ln_beta  = (const float*)d_in[2];
    const float* W_in     = (const float*)d_in[3];
    const float* b_in     = (const float*)d_in[4];
    const float* log_A    = (const float*)d_in[5];
    const float* B_p      = (const float*)d_in[6];
    const float* C_p      = (const float*)d_in[7];
    const float* D_p      = (const float*)d_in[8];
    const float* log_dt   = (const float*)d_in[9];
    const float* W_out    = (const float*)d_in[10];
    const float* b_out    = (const float*)d_in[11];
    float* out = (float*)d_out;

    float *xn, *u, *ysT;
    cudaGetSymbolAddress((void**)&xn,  g_xn);
    cudaGetSymbolAddress((void**)&u,   g_u);
    cudaGetSymbolAddress((void**)&ysT, g_ysT);

    ln_kernel<<<MROWS / 8, 256>>>(x, ln_gamma, ln_beta, xn);

    dim3 g1(DM / 64, MROWS / 64);   // (12, 64) = 768 blocks
    gemm_mma<false, false><<<g1, 128>>>(xn, W_in, b_in, nullptr, u);

    scan_kernel<<<BATCH * (DM / 4), 128>>>(u, log_A, B_p, C_p, D_p, log_dt, ysT);

    gemm_mma<true, true><<<g1, 128>>>(ysT, W_out, b_out, x, out);
}

// round 14
// speedup vs baseline: 1.1139x; 1.1139x over previous
#include <cuda_runtime.h>
#include <cstdint>
#include <math.h>

#define BATCH 2
#define SEQ   2048
#define DM    768
#define NS    64
#define MROWS (BATCH*SEQ)   // 4096

// Scratch (device globals)
__device__ float g_u   [MROWS*DM];   // in_proj output    [m][d]
__device__ float g_ysT [DM*MROWS];   // scan output, transposed [d][m]
__device__ float g_wp  [DM*DM];      // W_in * gamma
__device__ float g_wg  [DM];         // sum_k gamma[k]*W_in[n,k]
__device__ float g_wbb [DM];         // sum_k beta[k]*W_in[n,k] + b_in[n]
__device__ float g_inv [MROWS];      // 1/sqrt(var+eps) per row
__device__ float g_muiv[MROWS];      // mu*inv per row

__device__ __forceinline__ uint32_t smem_u32(const void* p) {
    uint32_t a;
    asm("{ .reg .u64 t; cvta.to.shared.u64 t, %1; cvt.u32.u64 %0, t; }"
        : "=r"(a) : "l"(p));
    return a;
}
__device__ __forceinline__ void cp16(uint32_t dst, const void* src) {
    asm volatile("cp.async.cg.shared.global [%0], [%1], 16;"
                 :: "r"(dst), "l"(src) : "memory");
}
#define CP_COMMIT() asm volatile("cp.async.commit_group;" ::: "memory")
#define CP_WAIT1()  asm volatile("cp.async.wait_group 1;" ::: "memory")

// ---------------------------------------------------------------------------
// LN stats: one warp per row -> inv[m], mu*inv[m]
// ---------------------------------------------------------------------------
__global__ void ln_stats(const float* __restrict__ x,
                         float* __restrict__ invv,
                         float* __restrict__ muiv) {
    int w = threadIdx.x >> 5, lane = threadIdx.x & 31;
    int row = blockIdx.x * 8 + w;
    const float4* xr = (const float4*)(x + (size_t)row * DM);
    float s = 0.f, s2 = 0.f;
    #pragma unroll
    for (int i = 0; i < 6; i++) {
        float4 v = xr[lane + 32 * i];
        s  += v.x + v.y + v.z + v.w;
        s2 += v.x*v.x + v.y*v.y + v.z*v.z + v.w*v.w;
    }
    #pragma unroll
    for (int o = 16; o; o >>= 1) {
        s  += __shfl_xor_sync(0xffffffffu, s,  o);
        s2 += __shfl_xor_sync(0xffffffffu, s2, o);
    }
    if (lane == 0) {
        float mu  = s * (1.0f / DM);
        float var = s2 * (1.0f / DM) - mu * mu;
        float inv = rsqrtf(var + 1e-5f);
        invv[row] = inv;
        muiv[row] = mu * inv;
    }
}

// ---------------------------------------------------------------------------
// Weight prep: Wp = W*gamma (per col k), wg[n] = sum gamma*W, wbb[n] = sum beta*W + b_in
// One warp per output row n.
// ---------------------------------------------------------------------------
__global__ void wprep(const float* __restrict__ W,
                      const float* __restrict__ gamma,
                      const float* __restrict__ beta,
                      const float* __restrict__ b_in,
                      float* __restrict__ Wp,
                      float* __restrict__ wg,
                      float* __restrict__ wbb) {
    int w = threadIdx.x >> 5, lane = threadIdx.x & 31;
    int n = blockIdx.x * 8 + w;
    const float4* wr = (const float4*)(W + (size_t)n * DM);
    const float4* g4 = (const float4*)gamma;
    const float4* b4 = (const float4*)beta;
    float4* wo = (float4*)(Wp + (size_t)n * DM);
    float sg = 0.f, sb = 0.f;
    #pragma unroll
    for (int i = 0; i < 6; i++) {
        float4 wv = wr[lane + 32 * i];
        float4 gv = g4[lane + 32 * i];
        float4 bv = b4[lane + 32 * i];
        float4 o;
        o.x = wv.x * gv.x; o.y = wv.y * gv.y; o.z = wv.z * gv.z; o.w = wv.w * gv.w;
        wo[lane + 32 * i] = o;
        sg += o.x + o.y + o.z + o.w;
        sb += wv.x*bv.x + wv.y*bv.y + wv.z*bv.z + wv.w*bv.w;
    }
    #pragma unroll
    for (int o = 16; o; o >>= 1) {
        sg += __shfl_xor_sync(0xffffffffu, sg, o);
        sb += __shfl_xor_sync(0xffffffffu, sb, o);
    }
    if (lane == 0) {
        wg[n]  = sg;
        wbb[n] = sb + b_in[n];
    }
}

// ---------------------------------------------------------------------------
// tf32 mma.sync GEMM, cp.async 3-stage pipeline (R12 config).
// Block 128x64, 128 threads (4 warps, 2m x 2n), warp tile 64x32.
// FUSE_LN: A is raw x; epilogue u = inv[m]*acc - muiv[m]*wg[n] + wbb[n]
//          (bias arg = wbb). ADD_RES: out = acc + bias + res.
// ---------------------------------------------------------------------------
#define STAGES 3

template<bool A_TRANS, bool ADD_RES, bool FUSE_LN>
__global__ __launch_bounds__(128, 4)
void gemm_mma(const float* __restrict__ A, const float* __restrict__ W,
              const float* __restrict__ bias, const float* __restrict__ res,
              float* __restrict__ C,
              const float* __restrict__ invv, const float* __restrict__ muiv,
              const float* __restrict__ wg) {
    constexpr int AS_FLOATS = A_TRANS ? (16 * 136) : (128 * 20);
    constexpr int BS_FLOATS = 64 * 20;
    __shared__ float As[STAGES][AS_FLOATS];
    __shared__ float Bs[STAGES][BS_FLOATS];

    const int tid = threadIdx.x;
    const int w = tid >> 5, lane = tid & 31;
    const int wm = (w & 1) * 64, wn = (w >> 1) * 32;
    const int g = lane >> 2, t = lane & 3;
    const int m0 = blockIdx.y * 128, n0 = blockIdx.x * 64;

    const uint32_t sA = smem_u32(&As[0][0]);
    const uint32_t sB = smem_u32(&Bs[0][0]);

    int aoff[4];
    const float* asrc[4];
    #pragma unroll
    for (int j = 0; j < 4; j++) {
        int f4 = tid + j * 128;  // 0..511
        if (A_TRANS) {
            int r = f4 >> 5, c = f4 & 31;
            aoff[j] = r * 136 + c * 4;
            asrc[j] = A + (size_t)r * MROWS + m0 + c * 4;
        } else {
            int r = f4 >> 2, c4 = f4 & 3;
            aoff[j] = r * 20 + c4 * 4;
            asrc[j] = A + (size_t)(m0 + r) * DM + c4 * 4;
        }
    }
    int boff[2];
    const float* bsrc[2];
    #pragma unroll
    for (int j = 0; j < 2; j++) {
        int f4 = tid + j * 128;  // 0..255
        int r = f4 >> 2, c4 = f4 & 3;
        boff[j] = r * 20 + c4 * 4;
        bsrc[j] = W + (size_t)(n0 + r) * DM + c4 * 4;
    }

    auto issue = [&](int kt) {
        int s = kt % STAGES;
        #pragma unroll
        for (int j = 0; j < 4; j++) {
            uint32_t dst = sA + (uint32_t)(s * AS_FLOATS + aoff[j]) * 4u;
            const float* src = asrc[j] + (A_TRANS ? (size_t)kt * 16 * MROWS
                                                  : (size_t)kt * 16);
            cp16(dst, src);
        }
        #pragma unroll
        for (int j = 0; j < 2; j++) {
            uint32_t dst = sB + (uint32_t)(s * BS_FLOATS + boff[j]) * 4u;
            cp16(dst, bsrc[j] + (size_t)kt * 16);
        }
    };

    issue(0); CP_COMMIT();
    issue(1); CP_COMMIT();

    float acc[4][4][4] = {};

    const int NKT = DM / 16;   // 48
    for (int kt = 0; kt < NKT; kt++) {
        CP_WAIT1();
        __syncthreads();
        int s = kt % STAGES;
        #pragma unroll
        for (int ks = 0; ks < 2; ks++) {
            uint32_t af[4][4], bf[4][2];
            #pragma unroll
            for (int mt = 0; mt < 4; mt++) {
                int m = wm + mt * 16;
                if (A_TRANS) {
                    af[mt][0] = __float_as_uint(As[s][(ks*8 + t)     * 136 + m + g]);
                    af[mt][1] = __float_as_uint(As[s][(ks*8 + t)     * 136 + m + g + 8]);
                    af[mt][2] = __float_as_uint(As[s][(ks*8 + t + 4) * 136 + m + g]);
                    af[mt][3] = __float_as_uint(As[s][(ks*8 + t + 4) * 136 + m + g + 8]);
                } else {
                    af[mt][0] = __float_as_uint(As[s][(m + g)     * 20 + ks*8 + t]);
                    af[mt][1] = __float_as_uint(As[s][(m + g + 8) * 20 + ks*8 + t]);
                    af[mt][2] = __float_as_uint(As[s][(m + g)     * 20 + ks*8 + t + 4]);
                    af[mt][3] = __float_as_uint(As[s][(m + g + 8) * 20 + ks*8 + t + 4]);
                }
            }
            #pragma unroll
            for (int nt = 0; nt < 4; nt++) {
                int n = wn + nt * 8;
                bf[nt][0] = __float_as_uint(Bs[s][(n + g) * 20 + ks*8 + t]);
                bf[nt][1] = __float_as_uint(Bs[s][(n + g) * 20 + ks*8 + t + 4]);
            }
            #pragma unroll
            for (int mt = 0; mt < 4; mt++)
                #pragma unroll
                for (int nt = 0; nt < 4; nt++)
                    asm volatile(
                        "mma.sync.aligned.m16n8k8.row.col.f32.tf32.tf32.f32 "
                        "{%0,%1,%2,%3}, {%4,%5,%6,%7}, {%8,%9}, {%0,%1,%2,%3};"
                        : "+f"(acc[mt][nt][0]), "+f"(acc[mt][nt][1]),
                          "+f"(acc[mt][nt][2]), "+f"(acc[mt][nt][3])
                        : "r"(af[mt][0]), "r"(af[mt][1]), "r"(af[mt][2]), "r"(af[mt][3]),
                          "r"(bf[nt][0]), "r"(bf[nt][1]));
        }
        if (kt + 2 < NKT) issue(kt + 2);
        CP_COMMIT();
    }

    // Epilogue
    #pragma unroll
    for (int mt = 0; mt < 4; mt++) {
        int r0 = m0 + wm + mt * 16 + g;
        float iva = 0.f, ivb = 0.f, mia = 0.f, mib = 0.f;
        if (FUSE_LN) {
            iva = invv[r0]; ivb = invv[r0 + 8];
            mia = muiv[r0]; mib = muiv[r0 + 8];
        }
        #pragma unroll
        for (int nt = 0; nt < 4; nt++) {
            int cn = n0 + wn + nt * 8 + t * 2;
            float2 bb = *(const float2*)(bias + cn);
            float2 o0, o1;
            if (FUSE_LN) {
                float2 wg2 = *(const float2*)(wg + cn);
                o0.x = fmaf(iva, acc[mt][nt][0], fmaf(-mia, wg2.x, bb.x));
                o0.y = fmaf(iva, acc[mt][nt][1], fmaf(-mia, wg2.y, bb.y));
                o1.x = fmaf(ivb, acc[mt][nt][2], fmaf(-mib, wg2.x, bb.x));
                o1.y = fmaf(ivb, acc[mt][nt][3], fmaf(-mib, wg2.y, bb.y));
            } else {
                o0 = make_float2(acc[mt][nt][0] + bb.x, acc[mt][nt][1] + bb.y);
                o1 = make_float2(acc[mt][nt][2] + bb.x, acc[mt][nt][3] + bb.y);
                if (ADD_RES) {
                    float2 ra = *(const float2*)(res + (size_t)r0 * DM + cn);
                    float2 rb = *(const float2*)(res + (size_t)(r0 + 8) * DM + cn);
                    o0.x += ra.x; o0.y += ra.y; o1.x += rb.x; o1.y += rb.y;
                }
            }
            *(float2*)(C + (size_t)r0 * DM + cn) = o0;
            *(float2*)(C + (size_t)(r0 + 8) * DM + cn) = o1;
        }
    }
}

// ---------------------------------------------------------------------------
// SSM scan (R12 structure, pad 33 -> 36 so each lane's reduce row is
// 16B-aligned and float4 loads are conflict-free).
// Block = 128 threads = 4 warps = 4 channels, grid 384.
// ---------------------------------------------------------------------------
__global__ __launch_bounds__(128)
void scan_kernel(const float* __restrict__ u,
                 const float* __restrict__ log_A,
                 const float* __restrict__ B_p,
                 const float* __restrict__ C_p,
                 const float* __restrict__ D_p,
                 const float* __restrict__ log_dt,
                 float* __restrict__ ysT) {
    __shared__ float red[4][32 * 36];

    int tid = threadIdx.x, w = tid >> 5, lane = tid & 31;
    int blk = blockIdx.x;
    int b  = blk / (DM / 4);
    int d  = (blk % (DM / 4)) * 4 + w;
    int n0 = lane * 2;

    float dt  = expf(log_dt[d]);
    float Ab0 = expf(dt * (-expf(log_A[d * NS + n0])));
    float Ab1 = expf(dt * (-expf(log_A[d * NS + n0 + 1])));
    float Cb0 = C_p[d * NS + n0]     * B_p[d * NS + n0]     * dt;
    float Cb1 = C_p[d * NS + n0 + 1] * B_p[d * NS + n0 + 1] * dt;
    float Dd  = D_p[d];

    const float* up = u + (size_t)b * SEQ * DM + d;
    float* yT = ysT + (size_t)d * MROWS + (size_t)b * SEQ;
    float* sm = &red[w][0];

    float e0 = 0.f, e1 = 0.f;
    float ul = __ldg(up + (size_t)lane * DM);

    for (int t0 = 0; t0 < SEQ; t0 += 32) {
        float uln = 0.f;
        if (t0 + 32 < SEQ)
            uln = __ldg(up + (size_t)(t0 + 32 + lane) * DM);

        #pragma unroll
        for (int i = 0; i < 32; i++) {
            float ut = __shfl_sync(0xffffffffu, ul, i);
            e0 = fmaf(Ab0, e0, ut);
            e1 = fmaf(Ab1, e1, ut);
            sm[i * 36 + lane] = fmaf(Cb0, e0, Cb1 * e1);
        }
        __syncwarp();

        float a0 = 0.f, a1 = 0.f, a2 = 0.f, a3 = 0.f;
        const float4* row = (const float4*)(sm + lane * 36);
        #pragma unroll
        for (int j = 0; j < 8; j++) {
            float4 v = row[j];
            a0 += v.x; a1 += v.y; a2 += v.z; a3 += v.w;
        }
        yT[t0 + lane] = fmaf(Dd, ul, (a0 + a1) + (a2 + a3));
        __syncwarp();

        ul = uln;
    }
}

// ---------------------------------------------------------------------------
extern "C" void kernel_launch(void* const* d_in, const int* in_sizes, int n_in,
                              void* d_out, int out_size) {
    const float* x        = (const float*)d_in[0];
    const float* ln_gamma = (const float*)d_in[1];
    const float* ln_beta  = (const float*)d_in[2];
    const float* W_in     = (const float*)d_in[3];
    const float* b_in     = (const float*)d_in[4];
    const float* log_A    = (const float*)d_in[5];
    const float* B_p      = (const float*)d_in[6];
    const float* C_p      = (const float*)d_in[7];
    const float* D_p      = (const float*)d_in[8];
    const float* log_dt   = (const float*)d_in[9];
    const float* W_out    = (const float*)d_in[10];
    const float* b_out    = (const float*)d_in[11];
    float* out = (float*)d_out;

    float *u, *ysT, *wp, *wg, *wbb, *invv, *muiv;
    cudaGetSymbolAddress((void**)&u,    g_u);
    cudaGetSymbolAddress((void**)&ysT,  g_ysT);
    cudaGetSymbolAddress((void**)&wp,   g_wp);
    cudaGetSymbolAddress((void**)&wg,   g_wg);
    cudaGetSymbolAddress((void**)&wbb,  g_wbb);
    cudaGetSymbolAddress((void**)&invv, g_inv);
    cudaGetSymbolAddress((void**)&muiv, g_muiv);

    ln_stats<<<MROWS / 8, 256>>>(x, invv, muiv);
    wprep<<<DM / 8, 256>>>(W_in, ln_gamma, ln_beta, b_in, wp, wg, wbb);

    dim3 g1(DM / 64, MROWS / 128);   // (12, 32) = 384 blocks
    // u = inv*(x @ Wp^T) - muiv*wg + wbb   (LN fused)
    gemm_mma<false, false, true><<<g1, 128>>>(x, wp, wbb, nullptr, u,
                                              invv, muiv, wg);

    scan_kernel<<<BATCH * (DM / 4), 128>>>(u, log_A, B_p, C_p, D_p, log_dt, ysT);

    gemm_mma<true, true, false><<<g1, 128>>>(ysT, W_out, b_out, x, out,
                                             nullptr, nullptr, nullptr);
}

// round 15
// speedup vs baseline: 1.1300x; 1.0144x over previous
#include <cuda_runtime.h>
#include <cstdint>
#include <math.h>

#define BATCH 2
#define SEQ   2048
#define DM    768
#define NS    64
#define MROWS (BATCH*SEQ)   // 4096

// Scratch (device globals)
__device__ float g_u   [MROWS*DM];   // in_proj output    [m][d]
__device__ float g_ysT [DM*MROWS];   // scan output, transposed [d][m]
__device__ float g_wp  [DM*DM];      // W_in * gamma
__device__ float g_wg  [DM];         // sum_k gamma[k]*W_in[n,k]
__device__ float g_wbb [DM];         // sum_k beta[k]*W_in[n,k] + b_in[n]
__device__ float g_inv [MROWS];      // 1/sqrt(var+eps) per row
__device__ float g_muiv[MROWS];      // mu*inv per row

__device__ __forceinline__ uint32_t smem_u32(const void* p) {
    uint32_t a;
    asm("{ .reg .u64 t; cvta.to.shared.u64 t, %1; cvt.u32.u64 %0, t; }"
        : "=r"(a) : "l"(p));
    return a;
}
__device__ __forceinline__ void cp16(uint32_t dst, const void* src) {
    asm volatile("cp.async.cg.shared.global [%0], [%1], 16;"
                 :: "r"(dst), "l"(src) : "memory");
}
#define CP_COMMIT() asm volatile("cp.async.commit_group;" ::: "memory")
#define CP_WAIT1()  asm volatile("cp.async.wait_group 1;" ::: "memory")

// ---------------------------------------------------------------------------
// LN stats: one warp per row -> inv[m], mu*inv[m]
// ---------------------------------------------------------------------------
__global__ void ln_stats(const float* __restrict__ x,
                         float* __restrict__ invv,
                         float* __restrict__ muiv) {
    int w = threadIdx.x >> 5, lane = threadIdx.x & 31;
    int row = blockIdx.x * 8 + w;
    const float4* xr = (const float4*)(x + (size_t)row * DM);
    float s = 0.f, s2 = 0.f;
    #pragma unroll
    for (int i = 0; i < 6; i++) {
        float4 v = xr[lane + 32 * i];
        s  += v.x + v.y + v.z + v.w;
        s2 += v.x*v.x + v.y*v.y + v.z*v.z + v.w*v.w;
    }
    #pragma unroll
    for (int o = 16; o; o >>= 1) {
        s  += __shfl_xor_sync(0xffffffffu, s,  o);
        s2 += __shfl_xor_sync(0xffffffffu, s2, o);
    }
    if (lane == 0) {
        float mu  = s * (1.0f / DM);
        float var = s2 * (1.0f / DM) - mu * mu;
        float inv = rsqrtf(var + 1e-5f);
        invv[row] = inv;
        muiv[row] = mu * inv;
    }
}

// ---------------------------------------------------------------------------
// Weight prep: Wp = W*gamma, wg[n] = sum gamma*W, wbb[n] = sum beta*W + b_in
// ---------------------------------------------------------------------------
__global__ void wprep(const float* __restrict__ W,
                      const float* __restrict__ gamma,
                      const float* __restrict__ beta,
                      const float* __restrict__ b_in,
                      float* __restrict__ Wp,
                      float* __restrict__ wg,
                      float* __restrict__ wbb) {
    int w = threadIdx.x >> 5, lane = threadIdx.x & 31;
    int n = blockIdx.x * 8 + w;
    const float4* wr = (const float4*)(W + (size_t)n * DM);
    const float4* g4 = (const float4*)gamma;
    const float4* b4 = (const float4*)beta;
    float4* wo = (float4*)(Wp + (size_t)n * DM);
    float sg = 0.f, sb = 0.f;
    #pragma unroll
    for (int i = 0; i < 6; i++) {
        float4 wv = wr[lane + 32 * i];
        float4 gv = g4[lane + 32 * i];
        float4 bv = b4[lane + 32 * i];
        float4 o;
        o.x = wv.x * gv.x; o.y = wv.y * gv.y; o.z = wv.z * gv.z; o.w = wv.w * gv.w;
        wo[lane + 32 * i] = o;
        sg += o.x + o.y + o.z + o.w;
        sb += wv.x*bv.x + wv.y*bv.y + wv.z*bv.z + wv.w*bv.w;
    }
    #pragma unroll
    for (int o = 16; o; o >>= 1) {
        sg += __shfl_xor_sync(0xffffffffu, sg, o);
        sb += __shfl_xor_sync(0xffffffffu, sb, o);
    }
    if (lane == 0) {
        wg[n]  = sg;
        wbb[n] = sb + b_in[n];
    }
}

// ---------------------------------------------------------------------------
// tf32 mma.sync GEMM, cp.async 3-stage pipeline (R12/R14 config).
// Block 128x64, 128 threads (4 warps, 2m x 2n), warp tile 64x32.
// ---------------------------------------------------------------------------
#define STAGES 3

template<bool A_TRANS, bool ADD_RES, bool FUSE_LN>
__global__ __launch_bounds__(128, 4)
void gemm_mma(const float* __restrict__ A, const float* __restrict__ W,
              const float* __restrict__ bias, const float* __restrict__ res,
              float* __restrict__ C,
              const float* __restrict__ invv, const float* __restrict__ muiv,
              const float* __restrict__ wg) {
    constexpr int AS_FLOATS = A_TRANS ? (16 * 136) : (128 * 20);
    constexpr int BS_FLOATS = 64 * 20;
    __shared__ float As[STAGES][AS_FLOATS];
    __shared__ float Bs[STAGES][BS_FLOATS];

    const int tid = threadIdx.x;
    const int w = tid >> 5, lane = tid & 31;
    const int wm = (w & 1) * 64, wn = (w >> 1) * 32;
    const int g = lane >> 2, t = lane & 3;
    const int m0 = blockIdx.y * 128, n0 = blockIdx.x * 64;

    const uint32_t sA = smem_u32(&As[0][0]);
    const uint32_t sB = smem_u32(&Bs[0][0]);

    int aoff[4];
    const float* asrc[4];
    #pragma unroll
    for (int j = 0; j < 4; j++) {
        int f4 = tid + j * 128;  // 0..511
        if (A_TRANS) {
            int r = f4 >> 5, c = f4 & 31;
            aoff[j] = r * 136 + c * 4;
            asrc[j] = A + (size_t)r * MROWS + m0 + c * 4;
        } else {
            int r = f4 >> 2, c4 = f4 & 3;
            aoff[j] = r * 20 + c4 * 4;
            asrc[j] = A + (size_t)(m0 + r) * DM + c4 * 4;
        }
    }
    int boff[2];
    const float* bsrc[2];
    #pragma unroll
    for (int j = 0; j < 2; j++) {
        int f4 = tid + j * 128;  // 0..255
        int r = f4 >> 2, c4 = f4 & 3;
        boff[j] = r * 20 + c4 * 4;
        bsrc[j] = W + (size_t)(n0 + r) * DM + c4 * 4;
    }

    auto issue = [&](int kt) {
        int s = kt % STAGES;
        #pragma unroll
        for (int j = 0; j < 4; j++) {
            uint32_t dst = sA + (uint32_t)(s * AS_FLOATS + aoff[j]) * 4u;
            const float* src = asrc[j] + (A_TRANS ? (size_t)kt * 16 * MROWS
                                                  : (size_t)kt * 16);
            cp16(dst, src);
        }
        #pragma unroll
        for (int j = 0; j < 2; j++) {
            uint32_t dst = sB + (uint32_t)(s * BS_FLOATS + boff[j]) * 4u;
            cp16(dst, bsrc[j] + (size_t)kt * 16);
        }
    };

    issue(0); CP_COMMIT();
    issue(1); CP_COMMIT();

    float acc[4][4][4] = {};

    const int NKT = DM / 16;   // 48
    for (int kt = 0; kt < NKT; kt++) {
        CP_WAIT1();
        __syncthreads();
        int s = kt % STAGES;
        #pragma unroll
        for (int ks = 0; ks < 2; ks++) {
            uint32_t af[4][4], bf[4][2];
            #pragma unroll
            for (int mt = 0; mt < 4; mt++) {
                int m = wm + mt * 16;
                if (A_TRANS) {
                    af[mt][0] = __float_as_uint(As[s][(ks*8 + t)     * 136 + m + g]);
                    af[mt][1] = __float_as_uint(As[s][(ks*8 + t)     * 136 + m + g + 8]);
                    af[mt][2] = __float_as_uint(As[s][(ks*8 + t + 4) * 136 + m + g]);
                    af[mt][3] = __float_as_uint(As[s][(ks*8 + t + 4) * 136 + m + g + 8]);
                } else {
                    af[mt][0] = __float_as_uint(As[s][(m + g)     * 20 + ks*8 + t]);
                    af[mt][1] = __float_as_uint(As[s][(m + g + 8) * 20 + ks*8 + t]);
                    af[mt][2] = __float_as_uint(As[s][(m + g)     * 20 + ks*8 + t + 4]);
                    af[mt][3] = __float_as_uint(As[s][(m + g + 8) * 20 + ks*8 + t + 4]);
                }
            }
            #pragma unroll
            for (int nt = 0; nt < 4; nt++) {
                int n = wn + nt * 8;
                bf[nt][0] = __float_as_uint(Bs[s][(n + g) * 20 + ks*8 + t]);
                bf[nt][1] = __float_as_uint(Bs[s][(n + g) * 20 + ks*8 + t + 4]);
            }
            #pragma unroll
            for (int mt = 0; mt < 4; mt++)
                #pragma unroll
                for (int nt = 0; nt < 4; nt++)
                    asm volatile(
                        "mma.sync.aligned.m16n8k8.row.col.f32.tf32.tf32.f32 "
                        "{%0,%1,%2,%3}, {%4,%5,%6,%7}, {%8,%9}, {%0,%1,%2,%3};"
                        : "+f"(acc[mt][nt][0]), "+f"(acc[mt][nt][1]),
                          "+f"(acc[mt][nt][2]), "+f"(acc[mt][nt][3])
                        : "r"(af[mt][0]), "r"(af[mt][1]), "r"(af[mt][2]), "r"(af[mt][3]),
                          "r"(bf[nt][0]), "r"(bf[nt][1]));
        }
        if (kt + 2 < NKT) issue(kt + 2);
        CP_COMMIT();
    }

    // Epilogue
    #pragma unroll
    for (int mt = 0; mt < 4; mt++) {
        int r0 = m0 + wm + mt * 16 + g;
        float iva = 0.f, ivb = 0.f, mia = 0.f, mib = 0.f;
        if (FUSE_LN) {
            iva = invv[r0]; ivb = invv[r0 + 8];
            mia = muiv[r0]; mib = muiv[r0 + 8];
        }
        #pragma unroll
        for (int nt = 0; nt < 4; nt++) {
            int cn = n0 + wn + nt * 8 + t * 2;
            float2 bb = *(const float2*)(bias + cn);
            float2 o0, o1;
            if (FUSE_LN) {
                float2 wg2 = *(const float2*)(wg + cn);
                o0.x = fmaf(iva, acc[mt][nt][0], fmaf(-mia, wg2.x, bb.x));
                o0.y = fmaf(iva, acc[mt][nt][1], fmaf(-mia, wg2.y, bb.y));
                o1.x = fmaf(ivb, acc[mt][nt][2], fmaf(-mib, wg2.x, bb.x));
                o1.y = fmaf(ivb, acc[mt][nt][3], fmaf(-mib, wg2.y, bb.y));
            } else {
                o0 = make_float2(acc[mt][nt][0] + bb.x, acc[mt][nt][1] + bb.y);
                o1 = make_float2(acc[mt][nt][2] + bb.x, acc[mt][nt][3] + bb.y);
                if (ADD_RES) {
                    float2 ra = *(const float2*)(res + (size_t)r0 * DM + cn);
                    float2 rb = *(const float2*)(res + (size_t)(r0 + 8) * DM + cn);
                    o0.x += ra.x; o0.y += ra.y; o1.x += rb.x; o1.y += rb.y;
                }
            }
            *(float2*)(C + (size_t)r0 * DM + cn) = o0;
            *(float2*)(C + (size_t)(r0 + 8) * DM + cn) = o1;
        }
    }
}

// ---------------------------------------------------------------------------
// SSM scan, register-tile version (no SHFL on the critical path).
// Block = 128 threads = 4 warps = 4 channels, grid 384.
// Per 32-step tile: lane STS's its u into a per-warp strip (double-buffered),
// 8x LDS.128 broadcast the strip into uu[32] registers, then the 32-step
// recurrence is pure FFMA. Partials go to a pad-36 transpose; lane L
// float4-reduces row L -> y[t0+L] (+ D*u from lane-local register).
// ---------------------------------------------------------------------------
__global__ __launch_bounds__(128)
void scan_kernel(const float* __restrict__ u,
                 const float* __restrict__ log_A,
                 const float* __restrict__ B_p,
                 const float* __restrict__ C_p,
                 const float* __restrict__ D_p,
                 const float* __restrict__ log_dt,
                 float* __restrict__ ysT) {
    __shared__ float red[4][32 * 36];
    __shared__ float su[4][2][32];

    int tid = threadIdx.x, w = tid >> 5, lane = tid & 31;
    int blk = blockIdx.x;
    int b  = blk / (DM / 4);
    int d  = (blk % (DM / 4)) * 4 + w;
    int n0 = lane * 2;

    float dt  = expf(log_dt[d]);
    float Ab0 = expf(dt * (-expf(log_A[d * NS + n0])));
    float Ab1 = expf(dt * (-expf(log_A[d * NS + n0 + 1])));
    float Cb0 = C_p[d * NS + n0]     * B_p[d * NS + n0]     * dt;
    float Cb1 = C_p[d * NS + n0 + 1] * B_p[d * NS + n0 + 1] * dt;
    float Dd  = D_p[d];

    const float* up = u + (size_t)b * SEQ * DM + d;
    float* yT = ysT + (size_t)d * MROWS + (size_t)b * SEQ;
    float* sm = &red[w][0];

    float e0 = 0.f, e1 = 0.f;

    // preload tile 0 into buffer 0
    float ul = __ldg(up + (size_t)lane * DM);
    su[w][0][lane] = ul;
    __syncwarp();

    for (int t0 = 0; t0 < SEQ; t0 += 32) {
        int buf = (t0 >> 5) & 1;

        // prefetch next tile's u (register), store to other buffer later
        float uln = 0.f;
        if (t0 + 32 < SEQ)
            uln = __ldg(up + (size_t)(t0 + 32 + lane) * DM);

        // broadcast-load the whole tile into registers: 8x LDS.128
        float uu[32];
        const float4* su4 = (const float4*)&su[w][buf][0];
        #pragma unroll
        for (int j = 0; j < 8; j++) {
            float4 v = su4[j];
            uu[j*4+0] = v.x; uu[j*4+1] = v.y; uu[j*4+2] = v.z; uu[j*4+3] = v.w;
        }

        #pragma unroll
        for (int i = 0; i < 32; i++) {
            e0 = fmaf(Ab0, e0, uu[i]);
            e1 = fmaf(Ab1, e1, uu[i]);
            sm[i * 36 + lane] = fmaf(Cb0, e0, Cb1 * e1);
        }

        // stage next tile while partials settle
        if (t0 + 32 < SEQ)
            su[w][buf ^ 1][lane] = uln;
        __syncwarp();

        float a0 = 0.f, a1 = 0.f, a2 = 0.f, a3 = 0.f;
        const float4* row = (const float4*)(sm + lane * 36);
        #pragma unroll
        for (int j = 0; j < 8; j++) {
            float4 v = row[j];
            a0 += v.x; a1 += v.y; a2 += v.z; a3 += v.w;
        }
        yT[t0 + lane] = fmaf(Dd, ul, (a0 + a1) + (a2 + a3));
        __syncwarp();

        ul = uln;
    }
}

// ---------------------------------------------------------------------------
extern "C" void kernel_launch(void* const* d_in, const int* in_sizes, int n_in,
                              void* d_out, int out_size) {
    const float* x        = (const float*)d_in[0];
    const float* ln_gamma = (const float*)d_in[1];
    const float* ln_beta  = (const float*)d_in[2];
    const float* W_in     = (const float*)d_in[3];
    const float* b_in     = (const float*)d_in[4];
    const float* log_A    = (const float*)d_in[5];
    const float* B_p      = (const float*)d_in[6];
    const float* C_p      = (const float*)d_in[7];
    const float* D_p      = (const float*)d_in[8];
    const float* log_dt   = (const float*)d_in[9];
    const float* W_out    = (const float*)d_in[10];
    const float* b_out    = (const float*)d_in[11];
    float* out = (float*)d_out;

    float *u, *ysT, *wp, *wg, *wbb, *invv, *muiv;
    cudaGetSymbolAddress((void**)&u,    g_u);
    cudaGetSymbolAddress((void**)&ysT,  g_ysT);
    cudaGetSymbolAddress((void**)&wp,   g_wp);
    cudaGetSymbolAddress((void**)&wg,   g_wg);
    cudaGetSymbolAddress((void**)&wbb,  g_wbb);
    cudaGetSymbolAddress((void**)&invv, g_inv);
    cudaGetSymbolAddress((void**)&muiv, g_muiv);

    ln_stats<<<MROWS / 8, 256>>>(x, invv, muiv);
    wprep<<<DM / 8, 256>>>(W_in, ln_gamma, ln_beta, b_in, wp, wg, wbb);

    dim3 g1(DM / 64, MROWS / 128);   // (12, 32) = 384 blocks
    gemm_mma<false, false, true><<<g1, 128>>>(x, wp, wbb, nullptr, u,
                                              invv, muiv, wg);

    scan_kernel<<<BATCH * (DM / 4), 128>>>(u, log_A, B_p, C_p, D_p, log_dt, ysT);

    gemm_mma<true, true, false><<<g1, 128>>>(ysT, W_out, b_out, x, out,
                                             nullptr, nullptr, nullptr);
}

// round 16
// speedup vs baseline: 1.2237x; 1.0829x over previous
#include <cuda_runtime.h>
#include <cstdint>
#include <math.h>

#define BATCH 2
#define SEQ   2048
#define DM    768
#define NS    64
#define MROWS (BATCH*SEQ)   // 4096

// Scratch (device globals)
__device__ float g_uT  [DM*MROWS];   // in_proj output, transposed [d][m]
__device__ float g_ysT [DM*MROWS];   // scan output, transposed [d][m]
__device__ float g_wp  [DM*DM];      // W_in * gamma
__device__ float g_wg  [DM];         // sum_k gamma[k]*W_in[n,k]
__device__ float g_wbb [DM];         // sum_k beta[k]*W_in[n,k] + b_in[n]
__device__ float g_inv [MROWS];      // 1/sqrt(var+eps) per row
__device__ float g_muiv[MROWS];      // mu*inv per row

__device__ __forceinline__ uint32_t smem_u32(const void* p) {
    uint32_t a;
    asm("{ .reg .u64 t; cvta.to.shared.u64 t, %1; cvt.u32.u64 %0, t; }"
        : "=r"(a) : "l"(p));
    return a;
}
__device__ __forceinline__ void cp16(uint32_t dst, const void* src) {
    asm volatile("cp.async.cg.shared.global [%0], [%1], 16;"
                 :: "r"(dst), "l"(src) : "memory");
}
#define CP_COMMIT() asm volatile("cp.async.commit_group;" ::: "memory")
#define CP_WAIT1()  asm volatile("cp.async.wait_group 1;" ::: "memory")
#define CP_WAIT0()  asm volatile("cp.async.wait_group 0;" ::: "memory")

// ---------------------------------------------------------------------------
// LN stats: one warp per row -> inv[m], mu*inv[m]
// ---------------------------------------------------------------------------
__global__ void ln_stats(const float* __restrict__ x,
                         float* __restrict__ invv,
                         float* __restrict__ muiv) {
    int w = threadIdx.x >> 5, lane = threadIdx.x & 31;
    int row = blockIdx.x * 8 + w;
    const float4* xr = (const float4*)(x + (size_t)row * DM);
    float s = 0.f, s2 = 0.f;
    #pragma unroll
    for (int i = 0; i < 6; i++) {
        float4 v = xr[lane + 32 * i];
        s  += v.x + v.y + v.z + v.w;
        s2 += v.x*v.x + v.y*v.y + v.z*v.z + v.w*v.w;
    }
    #pragma unroll
    for (int o = 16; o; o >>= 1) {
        s  += __shfl_xor_sync(0xffffffffu, s,  o);
        s2 += __shfl_xor_sync(0xffffffffu, s2, o);
    }
    if (lane == 0) {
        float mu  = s * (1.0f / DM);
        float var = s2 * (1.0f / DM) - mu * mu;
        float inv = rsqrtf(var + 1e-5f);
        invv[row] = inv;
        muiv[row] = mu * inv;
    }
}

// ---------------------------------------------------------------------------
// Weight prep: Wp = W*gamma, wg[n] = sum gamma*W, wbb[n] = sum beta*W + b_in
// ---------------------------------------------------------------------------
__global__ void wprep(const float* __restrict__ W,
                      const float* __restrict__ gamma,
                      const float* __restrict__ beta,
                      const float* __restrict__ b_in,
                      float* __restrict__ Wp,
                      float* __restrict__ wg,
                      float* __restrict__ wbb) {
    int w = threadIdx.x >> 5, lane = threadIdx.x & 31;
    int n = blockIdx.x * 8 + w;
    const float4* wr = (const float4*)(W + (size_t)n * DM);
    const float4* g4 = (const float4*)gamma;
    const float4* b4 = (const float4*)beta;
    float4* wo = (float4*)(Wp + (size_t)n * DM);
    float sg = 0.f, sb = 0.f;
    #pragma unroll
    for (int i = 0; i < 6; i++) {
        float4 wv = wr[lane + 32 * i];
        float4 gv = g4[lane + 32 * i];
        float4 bv = b4[lane + 32 * i];
        float4 o;
        o.x = wv.x * gv.x; o.y = wv.y * gv.y; o.z = wv.z * gv.z; o.w = wv.w * gv.w;
        wo[lane + 32 * i] = o;
        sg += o.x + o.y + o.z + o.w;
        sb += wv.x*bv.x + wv.y*bv.y + wv.z*bv.z + wv.w*bv.w;
    }
    #pragma unroll
    for (int o = 16; o; o >>= 1) {
        sg += __shfl_xor_sync(0xffffffffu, sg, o);
        sb += __shfl_xor_sync(0xffffffffu, sb, o);
    }
    if (lane == 0) {
        wg[n]  = sg;
        wbb[n] = sb + b_in[n];
    }
}

// ---------------------------------------------------------------------------
// tf32 mma.sync GEMM, cp.async 3-stage pipeline (R12 config).
// Block 128x64, 128 threads (4 warps, 2m x 2n), warp tile 64x32.
// STORE_T: epilogue stages the tile into (reused) smem as Ct[n][m] and
//          writes C in transposed layout CT[n][m] with coalesced STG.128.
// ---------------------------------------------------------------------------
#define STAGES 3

template<bool A_TRANS, bool ADD_RES, bool FUSE_LN, bool STORE_T>
__global__ __launch_bounds__(128, 4)
void gemm_mma(const float* __restrict__ A, const float* __restrict__ W,
              const float* __restrict__ bias, const float* __restrict__ res,
              float* __restrict__ C,
              const float* __restrict__ invv, const float* __restrict__ muiv,
              const float* __restrict__ wg) {
    constexpr int AS_FLOATS = A_TRANS ? (16 * 136) : (128 * 20);
    constexpr int BS_FLOATS = 64 * 20;
    constexpr int PIPE_FLOATS = STAGES * (AS_FLOATS + BS_FLOATS);
    constexpr int CT_FLOATS = STORE_T ? (64 * 132) : 0;
    constexpr int SM_FLOATS = PIPE_FLOATS > CT_FLOATS ? PIPE_FLOATS : CT_FLOATS;
    __shared__ float smem[SM_FLOATS];
    float* Asm = smem;                              // [STAGES][AS_FLOATS]
    float* Bsm = smem + STAGES * AS_FLOATS;         // [STAGES][BS_FLOATS]

    const int tid = threadIdx.x;
    const int w = tid >> 5, lane = tid & 31;
    const int wm = (w & 1) * 64, wn = (w >> 1) * 32;
    const int g = lane >> 2, t = lane & 3;
    const int m0 = blockIdx.y * 128, n0 = blockIdx.x * 64;

    const uint32_t sA = smem_u32(Asm);
    const uint32_t sB = smem_u32(Bsm);

    int aoff[4];
    const float* asrc[4];
    #pragma unroll
    for (int j = 0; j < 4; j++) {
        int f4 = tid + j * 128;  // 0..511
        if (A_TRANS) {
            int r = f4 >> 5, c = f4 & 31;
            aoff[j] = r * 136 + c * 4;
            asrc[j] = A + (size_t)r * MROWS + m0 + c * 4;
        } else {
            int r = f4 >> 2, c4 = f4 & 3;
            aoff[j] = r * 20 + c4 * 4;
            asrc[j] = A + (size_t)(m0 + r) * DM + c4 * 4;
        }
    }
    int boff[2];
    const float* bsrc[2];
    #pragma unroll
    for (int j = 0; j < 2; j++) {
        int f4 = tid + j * 128;  // 0..255
        int r = f4 >> 2, c4 = f4 & 3;
        boff[j] = r * 20 + c4 * 4;
        bsrc[j] = W + (size_t)(n0 + r) * DM + c4 * 4;
    }

    auto issue = [&](int kt) {
        int s = kt % STAGES;
        #pragma unroll
        for (int j = 0; j < 4; j++) {
            uint32_t dst = sA + (uint32_t)(s * AS_FLOATS + aoff[j]) * 4u;
            const float* src = asrc[j] + (A_TRANS ? (size_t)kt * 16 * MROWS
                                                  : (size_t)kt * 16);
            cp16(dst, src);
        }
        #pragma unroll
        for (int j = 0; j < 2; j++) {
            uint32_t dst = sB + (uint32_t)(s * BS_FLOATS + boff[j]) * 4u;
            cp16(dst, bsrc[j] + (size_t)kt * 16);
        }
    };

    issue(0); CP_COMMIT();
    issue(1); CP_COMMIT();

    float acc[4][4][4] = {};

    const int NKT = DM / 16;   // 48
    for (int kt = 0; kt < NKT; kt++) {
        CP_WAIT1();
        __syncthreads();
        int s = kt % STAGES;
        #pragma unroll
        for (int ks = 0; ks < 2; ks++) {
            uint32_t af[4][4], bf[4][2];
            #pragma unroll
            for (int mt = 0; mt < 4; mt++) {
                int m = wm + mt * 16;
                if (A_TRANS) {
                    af[mt][0] = __float_as_uint(Asm[s*AS_FLOATS + (ks*8 + t)     * 136 + m + g]);
                    af[mt][1] = __float_as_uint(Asm[s*AS_FLOATS + (ks*8 + t)     * 136 + m + g + 8]);
                    af[mt][2] = __float_as_uint(Asm[s*AS_FLOATS + (ks*8 + t + 4) * 136 + m + g]);
                    af[mt][3] = __float_as_uint(Asm[s*AS_FLOATS + (ks*8 + t + 4) * 136 + m + g + 8]);
                } else {
                    af[mt][0] = __float_as_uint(Asm[s*AS_FLOATS + (m + g)     * 20 + ks*8 + t]);
                    af[mt][1] = __float_as_uint(Asm[s*AS_FLOATS + (m + g + 8) * 20 + ks*8 + t]);
                    af[mt][2] = __float_as_uint(Asm[s*AS_FLOATS + (m + g)     * 20 + ks*8 + t + 4]);
                    af[mt][3] = __float_as_uint(Asm[s*AS_FLOATS + (m + g + 8) * 20 + ks*8 + t + 4]);
                }
            }
            #pragma unroll
            for (int nt = 0; nt < 4; nt++) {
                int n = wn + nt * 8;
                bf[nt][0] = __float_as_uint(Bsm[s*BS_FLOATS + (n + g) * 20 + ks*8 + t]);
                bf[nt][1] = __float_as_uint(Bsm[s*BS_FLOATS + (n + g) * 20 + ks*8 + t + 4]);
            }
            #pragma unroll
            for (int mt = 0; mt < 4; mt++)
                #pragma unroll
                for (int nt = 0; nt < 4; nt++)
                    asm volatile(
                        "mma.sync.aligned.m16n8k8.row.col.f32.tf32.tf32.f32 "
                        "{%0,%1,%2,%3}, {%4,%5,%6,%7}, {%8,%9}, {%0,%1,%2,%3};"
                        : "+f"(acc[mt][nt][0]), "+f"(acc[mt][nt][1]),
                          "+f"(acc[mt][nt][2]), "+f"(acc[mt][nt][3])
                        : "r"(af[mt][0]), "r"(af[mt][1]), "r"(af[mt][2]), "r"(af[mt][3]),
                          "r"(bf[nt][0]), "r"(bf[nt][1]));
        }
        if (kt + 2 < NKT) issue(kt + 2);
        CP_COMMIT();
    }

    // Epilogue
    if (STORE_T) {
        CP_WAIT0();
        __syncthreads();           // pipeline smem dead; reuse as Ct[64][132]
        float* Ct = smem;
        #pragma unroll
        for (int mt = 0; mt < 4; mt++) {
            int r0 = wm + mt * 16 + g;   // tile-local m
            float iva = 0.f, ivb = 0.f, mia = 0.f, mib = 0.f;
            if (FUSE_LN) {
                iva = invv[m0 + r0]; ivb = invv[m0 + r0 + 8];
                mia = muiv[m0 + r0]; mib = muiv[m0 + r0 + 8];
            }
            #pragma unroll
            for (int nt = 0; nt < 4; nt++) {
                int cn = wn + nt * 8 + t * 2;  // tile-local n
                float2 bb = *(const float2*)(bias + n0 + cn);
                float o0x, o0y, o1x, o1y;
                if (FUSE_LN) {
                    float2 wg2 = *(const float2*)(wg + n0 + cn);
                    o0x = fmaf(iva, acc[mt][nt][0], fmaf(-mia, wg2.x, bb.x));
                    o0y = fmaf(iva, acc[mt][nt][1], fmaf(-mia, wg2.y, bb.y));
                    o1x = fmaf(ivb, acc[mt][nt][2], fmaf(-mib, wg2.x, bb.x));
                    o1y = fmaf(ivb, acc[mt][nt][3], fmaf(-mib, wg2.y, bb.y));
                } else {
                    o0x = acc[mt][nt][0] + bb.x; o0y = acc[mt][nt][1] + bb.y;
                    o1x = acc[mt][nt][2] + bb.x; o1y = acc[mt][nt][3] + bb.y;
                }
                Ct[cn * 132 + r0]           = o0x;
                Ct[(cn + 1) * 132 + r0]     = o0y;
                Ct[cn * 132 + r0 + 8]       = o1x;
                Ct[(cn + 1) * 132 + r0 + 8] = o1y;
            }
        }
        __syncthreads();
        // coalesced transposed store: CT[n0+row][m0 + lane*4]
        #pragma unroll
        for (int it = 0; it < 16; it++) {
            int row = it * 4 + w;
            float4 v = *(const float4*)&Ct[row * 132 + lane * 4];
            *(float4*)(C + (size_t)(n0 + row) * MROWS + m0 + lane * 4) = v;
        }
    } else {
        #pragma unroll
        for (int mt = 0; mt < 4; mt++) {
            int r0 = m0 + wm + mt * 16 + g;
            #pragma unroll
            for (int nt = 0; nt < 4; nt++) {
                int cn = n0 + wn + nt * 8 + t * 2;
                float2 bb = *(const float2*)(bias + cn);
                float2 o0 = make_float2(acc[mt][nt][0] + bb.x, acc[mt][nt][1] + bb.y);
                float2 o1 = make_float2(acc[mt][nt][2] + bb.x, acc[mt][nt][3] + bb.y);
                if (ADD_RES) {
                    float2 ra = *(const float2*)(res + (size_t)r0 * DM + cn);
                    float2 rb = *(const float2*)(res + (size_t)(r0 + 8) * DM + cn);
                    o0.x += ra.x; o0.y += ra.y; o1.x += rb.x; o1.y += rb.y;
                }
                *(float2*)(C + (size_t)r0 * DM + cn) = o0;
                *(float2*)(C + (size_t)(r0 + 8) * DM + cn) = o1;
            }
        }
    }
}

// ---------------------------------------------------------------------------
// SSM scan, register-tile, COALESCED u loads (uT[d][m] layout).
// Block = 128 threads = 4 warps = 4 channels, grid 384.
// Per 32-step tile: coalesced LDG of 32 u values (1 line/warp), staged via
// per-warp smem strip + 8x LDS.128 broadcast into uu[32]; 32-step recurrence
// pure FFMA; partials to pad-36 transpose; lane L float4-reduces row L.
// ---------------------------------------------------------------------------
__global__ __launch_bounds__(128)
void scan_kernel(const float* __restrict__ uT,
                 const float* __restrict__ log_A,
                 const float* __restrict__ B_p,
                 const float* __restrict__ C_p,
                 const float* __restrict__ D_p,
                 const float* __restrict__ log_dt,
                 float* __restrict__ ysT) {
    __shared__ float red[4][32 * 36];
    __shared__ float su[4][2][32];

    int tid = threadIdx.x, w = tid >> 5, lane = tid & 31;
    int blk = blockIdx.x;
    int b  = blk / (DM / 4);
    int d  = (blk % (DM / 4)) * 4 + w;
    int n0 = lane * 2;

    float dt  = expf(log_dt[d]);
    float Ab0 = expf(dt * (-expf(log_A[d * NS + n0])));
    float Ab1 = expf(dt * (-expf(log_A[d * NS + n0 + 1])));
    float Cb0 = C_p[d * NS + n0]     * B_p[d * NS + n0]     * dt;
    float Cb1 = C_p[d * NS + n0 + 1] * B_p[d * NS + n0 + 1] * dt;
    float Dd  = D_p[d];

    const float* up = uT + (size_t)d * MROWS + (size_t)b * SEQ;
    float* yT = ysT + (size_t)d * MROWS + (size_t)b * SEQ;
    float* sm = &red[w][0];

    float e0 = 0.f, e1 = 0.f;

    float ul = __ldg(up + lane);            // coalesced: 1 line per warp
    su[w][0][lane] = ul;
    __syncwarp();

    for (int t0 = 0; t0 < SEQ; t0 += 32) {
        int buf = (t0 >> 5) & 1;

        float uln = 0.f;
        if (t0 + 32 < SEQ)
            uln = __ldg(up + t0 + 32 + lane);

        float uu[32];
        const float4* su4 = (const float4*)&su[w][buf][0];
        #pragma unroll
        for (int j = 0; j < 8; j++) {
            float4 v = su4[j];
            uu[j*4+0] = v.x; uu[j*4+1] = v.y; uu[j*4+2] = v.z; uu[j*4+3] = v.w;
        }

        #pragma unroll
        for (int i = 0; i < 32; i++) {
            e0 = fmaf(Ab0, e0, uu[i]);
            e1 = fmaf(Ab1, e1, uu[i]);
            sm[i * 36 + lane] = fmaf(Cb0, e0, Cb1 * e1);
        }

        if (t0 + 32 < SEQ)
            su[w][buf ^ 1][lane] = uln;
        __syncwarp();

        float a0 = 0.f, a1 = 0.f, a2 = 0.f, a3 = 0.f;
        const float4* row = (const float4*)(sm + lane * 36);
        #pragma unroll
        for (int j = 0; j < 8; j++) {
            float4 v = row[j];
            a0 += v.x; a1 += v.y; a2 += v.z; a3 += v.w;
        }
        yT[t0 + lane] = fmaf(Dd, ul, (a0 + a1) + (a2 + a3));
        __syncwarp();

        ul = uln;
    }
}

// ---------------------------------------------------------------------------
extern "C" void kernel_launch(void* const* d_in, const int* in_sizes, int n_in,
                              void* d_out, int out_size) {
    const float* x        = (const float*)d_in[0];
    const float* ln_gamma = (const float*)d_in[1];
    const float* ln_beta  = (const float*)d_in[2];
    const float* W_in     = (const float*)d_in[3];
    const float* b_in     = (const float*)d_in[4];
    const float* log_A    = (const float*)d_in[5];
    const float* B_p      = (const float*)d_in[6];
    const float* C_p      = (const float*)d_in[7];
    const float* D_p      = (const float*)d_in[8];
    const float* log_dt   = (const float*)d_in[9];
    const float* W_out    = (const float*)d_in[10];
    const float* b_out    = (const float*)d_in[11];
    float* out = (float*)d_out;

    float *uT, *ysT, *wp, *wg, *wbb, *invv, *muiv;
    cudaGetSymbolAddress((void**)&uT,   g_uT);
    cudaGetSymbolAddress((void**)&ysT,  g_ysT);
    cudaGetSymbolAddress((void**)&wp,   g_wp);
    cudaGetSymbolAddress((void**)&wg,   g_wg);
    cudaGetSymbolAddress((void**)&wbb,  g_wbb);
    cudaGetSymbolAddress((void**)&invv, g_inv);
    cudaGetSymbolAddress((void**)&muiv, g_muiv);

    ln_stats<<<MROWS / 8, 256>>>(x, invv, muiv);
    wprep<<<DM / 8, 256>>>(W_in, ln_gamma, ln_beta, b_in, wp, wg, wbb);

    dim3 g1(DM / 64, MROWS / 128);   // (12, 32) = 384 blocks
    // uT = transpose( inv*(x @ Wp^T) - muiv*wg + wbb )   (LN fused)
    gemm_mma<false, false, true, true><<<g1, 128>>>(x, wp, wbb, nullptr, uT,
                                                    invv, muiv, wg);

    scan_kernel<<<BATCH * (DM / 4), 128>>>(uT, log_A, B_p, C_p, D_p, log_dt, ysT);

    gemm_mma<true, true, false, false><<<g1, 128>>>(ysT, W_out, b_out, x, out,
                                                    nullptr, nullptr, nullptr);
}